// round 1
// baseline (speedup 1.0000x reference)
#include <cuda_runtime.h>
#include <math.h>

#define N_NODES 50000
#define NPAD    50048   // 391 * 128
#define FEAT    256

// ---------------- static scratch (no allocation allowed) ----------------
__device__ float g_hA[(size_t)NPAD * FEAT];
__device__ float g_hB[(size_t)NPAD * FEAT];
__device__ float g_agg[(size_t)NPAD * FEAT];
__device__ float g_t[(size_t)NPAD * FEAT];
__device__ float g_deg[NPAD];
__device__ float g_dis[NPAD];

// ---------------- degree / norm ----------------
__global__ void deg_init_kernel() {
    int i = blockIdx.x * blockDim.x + threadIdx.x;
    if (i < NPAD) g_deg[i] = 1.0f;   // self loop
}

__global__ void deg_count_kernel(const int* __restrict__ dst, int E) {
    int e = blockIdx.x * blockDim.x + threadIdx.x;
    if (e < E) atomicAdd(&g_deg[dst[e]], 1.0f);
}

__global__ void dis_kernel() {
    int i = blockIdx.x * blockDim.x + threadIdx.x;
    if (i < NPAD) g_dis[i] = (i < N_NODES) ? rsqrtf(g_deg[i]) : 0.0f;
}

// ---------------- agg init: agg = h * dis^2 (self-loop term), pad rows zero ----
template <int F4>
__global__ __launch_bounds__(256) void init_agg_kernel(const float4* __restrict__ h4,
                                                       float4* __restrict__ agg4) {
    int idx = blockIdx.x * 256 + threadIdx.x;
    const int total = NPAD * F4;
    if (idx >= total) return;
    int r = idx / F4;
    float4 o = make_float4(0.f, 0.f, 0.f, 0.f);
    if (r < N_NODES) {
        float dd = g_dis[r];
        float c = dd * dd;
        float4 hv = h4[idx];
        o = make_float4(hv.x * c, hv.y * c, hv.z * c, hv.w * c);
    }
    agg4[idx] = o;
}

// ---------------- edge scatter: agg[dst] += h[src] * dis[src]*dis[dst] --------
// one warp per edge; 128-bit vector reductions
template <int F4>
__global__ __launch_bounds__(256) void scatter_kernel(const float* __restrict__ h,
                                                      const int* __restrict__ src,
                                                      const int* __restrict__ dst,
                                                      int E,
                                                      float* __restrict__ agg) {
    int gw = (blockIdx.x * 256 + threadIdx.x) >> 5;
    if (gw >= E) return;
    int lane = threadIdx.x & 31;
    int s = __ldg(src + gw);
    int d = __ldg(dst + gw);
    float c = g_dis[s] * g_dis[d];
    const float4* hp = (const float4*)h + (size_t)s * F4 + lane;
    float4* ap = (float4*)agg + (size_t)d * F4 + lane;
#pragma unroll
    for (int it = 0; it < F4 / 32; it++) {
        float4 v = hp[it * 32];
        v.x *= c; v.y *= c; v.z *= c; v.w *= c;
        asm volatile("red.global.add.v4.f32 [%0], {%1,%2,%3,%4};"
                     :: "l"(ap + it * 32), "f"(v.x), "f"(v.y), "f"(v.z), "f"(v.w)
                     : "memory");
    }
}

// ---------------- SGEMM: C[NPAD,256] = A[NPAD,K] @ B[K,256] -------------------
// BM=128 BN=128 BK=8, 256 threads, 8x8 per-thread tile. NPAD%128==0, 256%128==0.
__global__ __launch_bounds__(256) void sgemm_kernel(const float* __restrict__ A,
                                                    const float* __restrict__ B,
                                                    float* __restrict__ C, int K) {
    __shared__ float As[8][128];
    __shared__ float Bs[8][128];
    const int tid = threadIdx.x;
    const int bx = blockIdx.x;   // N tile (0..1)
    const int by = blockIdx.y;   // M tile (0..390)
    const int trow = tid >> 4;   // 0..15
    const int tcol = tid & 15;   // 0..15

    const float* Ab = A + (size_t)(by * 128) * K;
    const float* Bb = B + bx * 128;

    const int a_row = tid >> 1;
    const int a_col = (tid & 1) * 4;
    const int b_row = tid >> 5;
    const int b_col = (tid & 31) * 4;

    float acc[8][8];
#pragma unroll
    for (int i = 0; i < 8; i++)
#pragma unroll
        for (int j = 0; j < 8; j++) acc[i][j] = 0.f;

    for (int k0 = 0; k0 < K; k0 += 8) {
        float4 av = *(const float4*)(Ab + (size_t)a_row * K + k0 + a_col);
        As[a_col + 0][a_row] = av.x;
        As[a_col + 1][a_row] = av.y;
        As[a_col + 2][a_row] = av.z;
        As[a_col + 3][a_row] = av.w;
        float4 bv = *(const float4*)(Bb + (size_t)(k0 + b_row) * 256 + b_col);
        *(float4*)&Bs[b_row][b_col] = bv;
        __syncthreads();
#pragma unroll
        for (int k = 0; k < 8; k++) {
            float ar[8], br[8];
#pragma unroll
            for (int i = 0; i < 8; i++) ar[i] = As[k][trow * 8 + i];
#pragma unroll
            for (int j = 0; j < 8; j++) br[j] = Bs[k][tcol * 8 + j];
#pragma unroll
            for (int i = 0; i < 8; i++)
#pragma unroll
                for (int j = 0; j < 8; j++) acc[i][j] += ar[i] * br[j];
        }
        __syncthreads();
    }

    float* Cb = C + (size_t)(by * 128 + trow * 8) * 256 + bx * 128 + tcol * 8;
#pragma unroll
    for (int i = 0; i < 8; i++) {
        *(float4*)(Cb + (size_t)i * 256) =
            make_float4(acc[i][0], acc[i][1], acc[i][2], acc[i][3]);
        *(float4*)(Cb + (size_t)i * 256 + 4) =
            make_float4(acc[i][4], acc[i][5], acc[i][6], acc[i][7]);
    }
}

// ---------------- fused epilogue: +bias, nan_to_num, LayerNorm, skip, relu ----
__device__ __forceinline__ float n2n(float x) {
    if (isnan(x)) return 0.0f;
    if (isinf(x)) return x > 0.0f ? 1e-5f : -1e-5f;
    return x;
}

__global__ __launch_bounds__(256) void post_kernel(const float* __restrict__ t,
                                                   const float* __restrict__ bias,
                                                   const float* __restrict__ gam,
                                                   const float* __restrict__ bet,
                                                   const float* __restrict__ hskip,
                                                   float* __restrict__ out,
                                                   int do_skip, int do_relu) {
    int node = blockIdx.x * 8 + (threadIdx.x >> 5);
    if (node >= N_NODES) return;
    int lane = threadIdx.x & 31;

    const float4* tp = (const float4*)(t + (size_t)node * 256) + lane * 2;
    const float4* bp = (const float4*)bias + lane * 2;
    float v[8], bb[8];
    *(float4*)&v[0] = tp[0];
    *(float4*)&v[4] = tp[1];
    *(float4*)&bb[0] = bp[0];
    *(float4*)&bb[4] = bp[1];

    float sum = 0.f;
#pragma unroll
    for (int i = 0; i < 8; i++) {
        v[i] = n2n(v[i] + bb[i]);
        sum += v[i];
    }
#pragma unroll
    for (int o = 16; o > 0; o >>= 1) sum += __shfl_xor_sync(0xFFFFFFFFu, sum, o);
    float mu = sum * (1.0f / 256.0f);

    float s2 = 0.f;
#pragma unroll
    for (int i = 0; i < 8; i++) {
        v[i] -= mu;
        s2 += v[i] * v[i];
    }
#pragma unroll
    for (int o = 16; o > 0; o >>= 1) s2 += __shfl_xor_sync(0xFFFFFFFFu, s2, o);
    float r = rsqrtf(s2 * (1.0f / 256.0f) + 1e-5f);

    const float4* gp = (const float4*)gam + lane * 2;
    const float4* ep = (const float4*)bet + lane * 2;
    float gg[8], ee[8];
    *(float4*)&gg[0] = gp[0];
    *(float4*)&gg[4] = gp[1];
    *(float4*)&ee[0] = ep[0];
    *(float4*)&ee[4] = ep[1];

    float y[8];
#pragma unroll
    for (int i = 0; i < 8; i++) y[i] = v[i] * r * gg[i] + ee[i];

    if (do_skip) {
        const float4* sp = (const float4*)(hskip + (size_t)node * 256) + lane * 2;
        float ss[8];
        *(float4*)&ss[0] = sp[0];
        *(float4*)&ss[4] = sp[1];
#pragma unroll
        for (int i = 0; i < 8; i++) y[i] += ss[i];
    }
    if (do_relu) {
#pragma unroll
        for (int i = 0; i < 8; i++) y[i] = fmaxf(y[i], 0.0f);
    }

    float4* op = (float4*)(out + (size_t)node * 256) + lane * 2;
    op[0] = make_float4(y[0], y[1], y[2], y[3]);
    op[1] = make_float4(y[4], y[5], y[6], y[7]);
}

// ---------------- host side ---------------------------------------------------
extern "C" void kernel_launch(void* const* d_in, const int* in_sizes, int n_in,
                              void* d_out, int out_size) {
    const float* x = (const float*)d_in[0];
    const int* ei = (const int*)d_in[1];
    const int E = in_sizes[1] / 2;
    const int* src = ei;
    const int* dst = ei + E;

    // Detect input ordering: dict order (W,b,g,be per layer) vs signature order
    const float *W[4], *Bv[4], *G[4], *BE[4];
    bool sig_order = (in_sizes[4] > 1024);  // signature order => d_in[4] is W1 (65536)
    if (!sig_order) {
        for (int i = 0; i < 4; i++) {
            W[i]  = (const float*)d_in[2 + 4 * i];
            Bv[i] = (const float*)d_in[3 + 4 * i];
            G[i]  = (const float*)d_in[4 + 4 * i];
            BE[i] = (const float*)d_in[5 + 4 * i];
        }
    } else {
        for (int i = 0; i < 4; i++) {
            W[i]  = (const float*)d_in[2 + 2 * i];
            Bv[i] = (const float*)d_in[3 + 2 * i];
            G[i]  = (const float*)d_in[10 + 2 * i];
            BE[i] = (const float*)d_in[11 + 2 * i];
        }
    }

    float *hA, *hB, *agg, *t;
    cudaGetSymbolAddress((void**)&hA, g_hA);
    cudaGetSymbolAddress((void**)&hB, g_hB);
    cudaGetSymbolAddress((void**)&agg, g_agg);
    cudaGetSymbolAddress((void**)&t, g_t);
    float* out = (float*)d_out;

    // degrees / normalization coefficients
    deg_init_kernel<<<(NPAD + 255) / 256, 256>>>();
    deg_count_kernel<<<(E + 255) / 256, 256>>>(dst, E);
    dis_kernel<<<(NPAD + 255) / 256, 256>>>();

    const int scat_blocks = (E * 32 + 255) / 256;
    dim3 gemm_grid(2, NPAD / 128);

    // ---- layer 0: in = x (128 feats), out -> hA, no skip, relu ----
    init_agg_kernel<32><<<(NPAD * 32 + 255) / 256, 256>>>((const float4*)x, (float4*)agg);
    scatter_kernel<32><<<scat_blocks, 256>>>(x, src, dst, E, agg);
    sgemm_kernel<<<gemm_grid, 256>>>(agg, W[0], t, 128);
    post_kernel<<<(N_NODES + 7) / 8, 256>>>(t, Bv[0], G[0], BE[0], nullptr, hA, 0, 1);

    // ---- layer 1: in = hA, out -> hB, skip hA, relu ----
    init_agg_kernel<64><<<(NPAD * 64 + 255) / 256, 256>>>((const float4*)hA, (float4*)agg);
    scatter_kernel<64><<<scat_blocks, 256>>>(hA, src, dst, E, agg);
    sgemm_kernel<<<gemm_grid, 256>>>(agg, W[1], t, 256);
    post_kernel<<<(N_NODES + 7) / 8, 256>>>(t, Bv[1], G[1], BE[1], hA, hB, 1, 1);

    // ---- layer 2: in = hB, out -> hA, skip hB, relu ----
    init_agg_kernel<64><<<(NPAD * 64 + 255) / 256, 256>>>((const float4*)hB, (float4*)agg);
    scatter_kernel<64><<<scat_blocks, 256>>>(hB, src, dst, E, agg);
    sgemm_kernel<<<gemm_grid, 256>>>(agg, W[2], t, 256);
    post_kernel<<<(N_NODES + 7) / 8, 256>>>(t, Bv[2], G[2], BE[2], hB, hA, 1, 1);

    // ---- layer 3: in = hA, out -> d_out, skip hA, no relu ----
    init_agg_kernel<64><<<(NPAD * 64 + 255) / 256, 256>>>((const float4*)hA, (float4*)agg);
    scatter_kernel<64><<<scat_blocks, 256>>>(hA, src, dst, E, agg);
    sgemm_kernel<<<gemm_grid, 256>>>(agg, W[3], t, 256);
    post_kernel<<<(N_NODES + 7) / 8, 256>>>(t, Bv[3], G[3], BE[3], hA, out, 1, 0);
}

// round 2
// speedup vs baseline: 1.5199x; 1.5199x over previous
#include <cuda_runtime.h>
#include <math.h>

#define N_NODES 50000
#define NPAD    50048   // 391 * 128
#define FEAT    256
#define E_MAX   1600000

// ---------------- static scratch (no allocation allowed) ----------------
__device__ float g_hA[(size_t)NPAD * FEAT];
__device__ float g_hB[(size_t)NPAD * FEAT];
__device__ float g_agg[(size_t)NPAD * FEAT];
__device__ float g_dis[NPAD];
__device__ int   g_cnt[NPAD];
__device__ int   g_row_ptr[NPAD + 1];
__device__ int   g_cursor[NPAD];
__device__ int   g_csr_src[E_MAX];
__device__ float g_csr_c[E_MAX];

// ---------------- degree / CSR construction ----------------
__global__ void cnt_init_kernel() {
    int i = blockIdx.x * blockDim.x + threadIdx.x;
    if (i < NPAD) g_cnt[i] = 0;
}

__global__ void deg_count_kernel(const int* __restrict__ dst, int E) {
    int e = blockIdx.x * blockDim.x + threadIdx.x;
    if (e < E) atomicAdd(&g_cnt[dst[e]], 1);
}

__global__ void dis_kernel() {
    int i = blockIdx.x * blockDim.x + threadIdx.x;
    if (i < NPAD) g_dis[i] = (i < N_NODES) ? rsqrtf((float)(g_cnt[i] + 1)) : 0.0f;
}

// single-block exclusive scan of g_cnt -> g_row_ptr / g_cursor
__global__ void scan_kernel(int E) {
    __shared__ int sh[1024];
    __shared__ int carry_sh;
    int tid = threadIdx.x;
    if (tid == 0) carry_sh = 0;
    __syncthreads();
    for (int base = 0; base < NPAD; base += 1024) {
        int i = base + tid;
        int v = (i < NPAD) ? g_cnt[i] : 0;
        sh[tid] = v;
        __syncthreads();
        for (int off = 1; off < 1024; off <<= 1) {
            int t = (tid >= off) ? sh[tid - off] : 0;
            __syncthreads();
            sh[tid] += t;
            __syncthreads();
        }
        int c = carry_sh;
        if (i < NPAD) {
            int ex = c + sh[tid] - v;
            g_row_ptr[i] = ex;
            g_cursor[i] = ex;
        }
        int tot = sh[1023];
        __syncthreads();
        if (tid == 0) carry_sh = c + tot;
        __syncthreads();
    }
    if (tid == 0) g_row_ptr[NPAD] = E;
}

__global__ void fill_kernel(const int* __restrict__ src, const int* __restrict__ dst, int E) {
    int e = blockIdx.x * blockDim.x + threadIdx.x;
    if (e >= E) return;
    int s = src[e];
    int d = dst[e];
    int pos = atomicAdd(&g_cursor[d], 1);
    g_csr_src[pos] = s;
    g_csr_c[pos] = g_dis[s];
}

// ---------------- CSR gather: agg[d] = dis[d]*(sum_{s in N(d)} dis[s]*h[s] + dis[d]*h[d])
// one warp per destination node; register accumulation; single write per row.
template <int F4>
__global__ __launch_bounds__(256) void gather_kernel(const float* __restrict__ h,
                                                     float* __restrict__ agg) {
    const int VPL = F4 / 32;  // float4 vectors per lane (1 for F=128, 2 for F=256)
    int node = blockIdx.x * 8 + (threadIdx.x >> 5);
    if (node >= NPAD) return;
    int lane = threadIdx.x & 31;
    float4* ap = (float4*)agg + (size_t)node * F4 + lane;

    if (node >= N_NODES) {
        float4 z = make_float4(0.f, 0.f, 0.f, 0.f);
#pragma unroll
        for (int v = 0; v < VPL; v++) ap[32 * v] = z;
        return;
    }

    const float4* h4 = (const float4*)h;
    float dd = g_dis[node];

    float4 acc[VPL];
    {
        const float4* hn = h4 + (size_t)node * F4 + lane;
#pragma unroll
        for (int v = 0; v < VPL; v++) {
            float4 t = hn[32 * v];
            acc[v] = make_float4(t.x * dd, t.y * dd, t.z * dd, t.w * dd);
        }
    }

    int beg = g_row_ptr[node];
    int end = g_row_ptr[node + 1];
    int e = beg;
    int n4 = beg + ((end - beg) & ~3);
    for (; e < n4; e += 4) {
        int s0 = g_csr_src[e + 0], s1 = g_csr_src[e + 1];
        int s2 = g_csr_src[e + 2], s3 = g_csr_src[e + 3];
        float c0 = g_csr_c[e + 0], c1 = g_csr_c[e + 1];
        float c2 = g_csr_c[e + 2], c3 = g_csr_c[e + 3];
#pragma unroll
        for (int v = 0; v < VPL; v++) {
            float4 x0 = h4[(size_t)s0 * F4 + lane + 32 * v];
            float4 x1 = h4[(size_t)s1 * F4 + lane + 32 * v];
            float4 x2 = h4[(size_t)s2 * F4 + lane + 32 * v];
            float4 x3 = h4[(size_t)s3 * F4 + lane + 32 * v];
            acc[v].x += c0 * x0.x + c1 * x1.x + c2 * x2.x + c3 * x3.x;
            acc[v].y += c0 * x0.y + c1 * x1.y + c2 * x2.y + c3 * x3.y;
            acc[v].z += c0 * x0.z + c1 * x1.z + c2 * x2.z + c3 * x3.z;
            acc[v].w += c0 * x0.w + c1 * x1.w + c2 * x2.w + c3 * x3.w;
        }
    }
    for (; e < end; e++) {
        int s = g_csr_src[e];
        float c = g_csr_c[e];
#pragma unroll
        for (int v = 0; v < VPL; v++) {
            float4 x = h4[(size_t)s * F4 + lane + 32 * v];
            acc[v].x += c * x.x;
            acc[v].y += c * x.y;
            acc[v].z += c * x.z;
            acc[v].w += c * x.w;
        }
    }

#pragma unroll
    for (int v = 0; v < VPL; v++) {
        ap[32 * v] = make_float4(acc[v].x * dd, acc[v].y * dd, acc[v].z * dd, acc[v].w * dd);
    }
}

// ---------------- fused SGEMM + bias + nan_to_num + LayerNorm + skip + relu ---
// C[128,256] tile per block = A[128,K] @ W[K,256]; full output width per block
// so each warp owns complete rows -> LayerNorm via warp shuffles.
__device__ __forceinline__ float n2n(float x) {
    if (isnan(x)) return 0.0f;
    if (isinf(x)) return x > 0.0f ? 1e-5f : -1e-5f;
    return x;
}

__global__ __launch_bounds__(512, 1) void gemm_ln_kernel(const float* __restrict__ A,
                                                         const float* __restrict__ W,
                                                         const float* __restrict__ bias,
                                                         const float* __restrict__ gam,
                                                         const float* __restrict__ bet,
                                                         const float* __restrict__ hskip,
                                                         float* __restrict__ out,
                                                         int K, int do_skip, int do_relu) {
    __shared__ float As[8][128];
    __shared__ float Bs[8][256];
    const int tid = threadIdx.x;
    const int by = blockIdx.x;
    const int r16 = tid >> 5;    // 0..15 : row group
    const int lane = tid & 31;   // column group (8 cols each)

    const float* Ab = A + (size_t)(by * 128) * K;

    const int a_row = tid >> 1;
    const int a_col = (tid & 1) * 4;
    const int b_row = tid >> 6;
    const int b_col = (tid & 63) * 4;

    float acc[8][8];
#pragma unroll
    for (int i = 0; i < 8; i++)
#pragma unroll
        for (int j = 0; j < 8; j++) acc[i][j] = 0.f;

    for (int k0 = 0; k0 < K; k0 += 8) {
        if (tid < 256) {
            float4 av = *(const float4*)(Ab + (size_t)a_row * K + k0 + a_col);
            As[a_col + 0][a_row] = av.x;
            As[a_col + 1][a_row] = av.y;
            As[a_col + 2][a_row] = av.z;
            As[a_col + 3][a_row] = av.w;
        }
        float4 bv = *(const float4*)(W + (size_t)(k0 + b_row) * 256 + b_col);
        *(float4*)&Bs[b_row][b_col] = bv;
        __syncthreads();
#pragma unroll
        for (int k = 0; k < 8; k++) {
            float4 a0 = *(const float4*)&As[k][r16 * 8];
            float4 a1 = *(const float4*)&As[k][r16 * 8 + 4];
            float4 b0 = *(const float4*)&Bs[k][lane * 8];
            float4 b1 = *(const float4*)&Bs[k][lane * 8 + 4];
            float ar[8] = {a0.x, a0.y, a0.z, a0.w, a1.x, a1.y, a1.z, a1.w};
            float br[8] = {b0.x, b0.y, b0.z, b0.w, b1.x, b1.y, b1.z, b1.w};
#pragma unroll
            for (int i = 0; i < 8; i++)
#pragma unroll
                for (int j = 0; j < 8; j++) acc[i][j] += ar[i] * br[j];
        }
        __syncthreads();
    }

    // per-column parameters for this thread's 8 columns
    float bb[8], gg[8], ee[8];
    {
        const float4* bp = (const float4*)bias + lane * 2;
        const float4* gp = (const float4*)gam + lane * 2;
        const float4* ep = (const float4*)bet + lane * 2;
        *(float4*)&bb[0] = bp[0]; *(float4*)&bb[4] = bp[1];
        *(float4*)&gg[0] = gp[0]; *(float4*)&gg[4] = gp[1];
        *(float4*)&ee[0] = ep[0]; *(float4*)&ee[4] = ep[1];
    }

#pragma unroll
    for (int i = 0; i < 8; i++) {
        int grow = by * 128 + r16 * 8 + i;

        float v[8];
        float sum = 0.f;
#pragma unroll
        for (int j = 0; j < 8; j++) {
            v[j] = n2n(acc[i][j] + bb[j]);
            sum += v[j];
        }
#pragma unroll
        for (int o = 16; o > 0; o >>= 1) sum += __shfl_xor_sync(0xFFFFFFFFu, sum, o);
        float mu = sum * (1.0f / 256.0f);

        float s2 = 0.f;
#pragma unroll
        for (int j = 0; j < 8; j++) {
            v[j] -= mu;
            s2 += v[j] * v[j];
        }
#pragma unroll
        for (int o = 16; o > 0; o >>= 1) s2 += __shfl_xor_sync(0xFFFFFFFFu, s2, o);
        float r = rsqrtf(s2 * (1.0f / 256.0f) + 1e-5f);

        float y[8];
#pragma unroll
        for (int j = 0; j < 8; j++) y[j] = v[j] * r * gg[j] + ee[j];

        if (grow < N_NODES) {
            if (do_skip) {
                const float4* sp = (const float4*)(hskip + (size_t)grow * 256) + lane * 2;
                float4 s0 = sp[0], s1 = sp[1];
                y[0] += s0.x; y[1] += s0.y; y[2] += s0.z; y[3] += s0.w;
                y[4] += s1.x; y[5] += s1.y; y[6] += s1.z; y[7] += s1.w;
            }
            if (do_relu) {
#pragma unroll
                for (int j = 0; j < 8; j++) y[j] = fmaxf(y[j], 0.0f);
            }
            float4* op = (float4*)(out + (size_t)grow * 256) + lane * 2;
            op[0] = make_float4(y[0], y[1], y[2], y[3]);
            op[1] = make_float4(y[4], y[5], y[6], y[7]);
        }
    }
}

// ---------------- host side ---------------------------------------------------
extern "C" void kernel_launch(void* const* d_in, const int* in_sizes, int n_in,
                              void* d_out, int out_size) {
    const float* x = (const float*)d_in[0];
    const int* ei = (const int*)d_in[1];
    const int E = in_sizes[1] / 2;
    const int* src = ei;
    const int* dst = ei + E;

    // Detect input ordering: dict order (W,b,g,be per layer) vs signature order
    const float *W[4], *Bv[4], *G[4], *BE[4];
    bool sig_order = (in_sizes[4] > 1024);
    if (!sig_order) {
        for (int i = 0; i < 4; i++) {
            W[i]  = (const float*)d_in[2 + 4 * i];
            Bv[i] = (const float*)d_in[3 + 4 * i];
            G[i]  = (const float*)d_in[4 + 4 * i];
            BE[i] = (const float*)d_in[5 + 4 * i];
        }
    } else {
        for (int i = 0; i < 4; i++) {
            W[i]  = (const float*)d_in[2 + 2 * i];
            Bv[i] = (const float*)d_in[3 + 2 * i];
            G[i]  = (const float*)d_in[10 + 2 * i];
            BE[i] = (const float*)d_in[11 + 2 * i];
        }
    }

    float *hA, *hB, *agg;
    cudaGetSymbolAddress((void**)&hA, g_hA);
    cudaGetSymbolAddress((void**)&hB, g_hB);
    cudaGetSymbolAddress((void**)&agg, g_agg);
    float* out = (float*)d_out;

    // build normalization + CSR
    cnt_init_kernel<<<(NPAD + 255) / 256, 256>>>();
    deg_count_kernel<<<(E + 255) / 256, 256>>>(dst, E);
    dis_kernel<<<(NPAD + 255) / 256, 256>>>();
    scan_kernel<<<1, 1024>>>(E);
    fill_kernel<<<(E + 255) / 256, 256>>>(src, dst, E);

    const int gather_grid = NPAD / 8;
    const int gemm_grid = NPAD / 128;

    // layer 0: x (128) -> hA, no skip, relu
    gather_kernel<32><<<gather_grid, 256>>>(x, agg);
    gemm_ln_kernel<<<gemm_grid, 512>>>(agg, W[0], Bv[0], G[0], BE[0], nullptr, hA, 128, 0, 1);

    // layer 1: hA -> hB, skip hA, relu
    gather_kernel<64><<<gather_grid, 256>>>(hA, agg);
    gemm_ln_kernel<<<gemm_grid, 512>>>(agg, W[1], Bv[1], G[1], BE[1], hA, hB, 256, 1, 1);

    // layer 2: hB -> hA, skip hB, relu
    gather_kernel<64><<<gather_grid, 256>>>(hB, agg);
    gemm_ln_kernel<<<gemm_grid, 512>>>(agg, W[2], Bv[2], G[2], BE[2], hB, hA, 256, 1, 1);

    // layer 3: hA -> d_out, skip hA, no relu
    gather_kernel<64><<<gather_grid, 256>>>(hA, agg);
    gemm_ln_kernel<<<gemm_grid, 512>>>(agg, W[3], Bv[3], G[3], BE[3], hA, out, 256, 1, 0);
}